// round 4
// baseline (speedup 1.0000x reference)
#include <cuda_runtime.h>

#define TPB     256
#define NBLOCKS 1216     // 152 SMs * 8 resident blocks (regs<=32): one wave
#define W       512      // column-strip width (= 2 * TPB)
#define H       4        // rows per tile (= unroll depth)

// ---------------------------------------------------------------------------
// out = sum_j x[j] * ( c1[j] + sum_{i<j} x[i] * c2[base(i) + (j-i-1)] )
// c2 = c + n, base(i) = i*(2n-1-i)/2  (row-major packed upper triangle).
//
// Tile f -> (strip js, row-tile it): strip js has 128*(js+1) row-tiles,
// prefix(js) = 64*js*(js+1). Thread t owns columns j_a = js*W + t and
// j_b = j_a + TPB with one register accumulator each; the inner loop reads
// only the coeff stream (coalesced, evict-first) + one uniform x[i] per row.
// ---------------------------------------------------------------------------

__global__ void zero_out_kernel(float* out) {
    if (threadIdx.x == 0 && blockIdx.x == 0) out[0] = 0.0f;
}

__device__ __forceinline__ float warp_sum(float v) {
    #pragma unroll
    for (int o = 16; o > 0; o >>= 1) v += __shfl_down_sync(0xffffffffu, v, o);
    return v;
}

__global__ __launch_bounds__(TPB, 8)
void ham_kernel(const float* __restrict__ x,
                const float* __restrict__ c,
                float* __restrict__ out,
                int n) {
    const int t = threadIdx.x;
    const float* c2 = c + n;

    const int nstrips = n / W;                                   // 16
    const int ntiles  = (W / H / 2) * nstrips * (nstrips + 1);   // 17408

    float sum = 0.0f;

    for (int f = blockIdx.x; f < ntiles; f += gridDim.x) {
        // analytic strip lookup: largest js with 64*js*(js+1) <= f
        int js = (int)((__fsqrt_rn((float)f * 0.015625f + 1.0f) - 1.0f) * 0.5f);
        while (64 * (js + 1) * (js + 2) <= f) ++js;   // fixup (<=1 iter)
        while (64 * js * (js + 1) > f) --js;
        const int it = f - 64 * js * (js + 1);

        const int j0  = js * W;
        const int i0  = it * H;
        const int j_a = j0 + t;
        const int j_b = j_a + TPB;

        float acc0 = 0.0f, acc1 = 0.0f;
        if (it == 0) {                       // fold degree-1 terms in once
            acc0 = __ldg(c + j_a);
            acc1 = __ldg(c + j_b);
        }

        const int base = (i0 * (2 * n - 1 - i0)) >> 1;   // < 2^27, exact
        const float* p = c2 + base + (j_a - i0 - 1);

        if (i0 + H <= j0) {
            // ---- clean path: whole tile strictly above diagonal ----
            const int o1 = n - 2 - i0;
            const int o2 = 2 * n - 5 - 2 * i0;
            const int o3 = 3 * n - 9 - 3 * i0;
            const float xi0 = __ldg(x + i0);
            const float xi1 = __ldg(x + i0 + 1);
            const float xi2 = __ldg(x + i0 + 2);
            const float xi3 = __ldg(x + i0 + 3);
            // 8 independent streaming loads in flight
            const float a0 = __ldcs(p);
            const float b0 = __ldcs(p + TPB);
            const float a1 = __ldcs(p + o1);
            const float b1 = __ldcs(p + o1 + TPB);
            const float a2 = __ldcs(p + o2);
            const float b2 = __ldcs(p + o2 + TPB);
            const float a3 = __ldcs(p + o3);
            const float b3 = __ldcs(p + o3 + TPB);
            acc0 = fmaf(xi0, a0, acc0);  acc1 = fmaf(xi0, b0, acc1);
            acc0 = fmaf(xi1, a1, acc0);  acc1 = fmaf(xi1, b1, acc1);
            acc0 = fmaf(xi2, a2, acc0);  acc1 = fmaf(xi2, b2, acc1);
            acc0 = fmaf(xi3, a3, acc0);  acc1 = fmaf(xi3, b3, acc1);
        } else {
            // ---- diagonal path: predicate j > i per element ----
            int iend = i0 + H;
            const int ilim = (js + 1) * W - 1;   // rows valid while i < ilim
            if (iend > ilim) iend = ilim;
            const float* q = p;
            for (int i = i0; i < iend; ++i) {
                const float xi = __ldg(x + i);
                float ca = 0.0f, cb = 0.0f;
                if (j_a > i) ca = __ldcs(q);
                if (j_b > i) cb = __ldcs(q + TPB);
                acc0 = fmaf(xi, ca, acc0);
                acc1 = fmaf(xi, cb, acc1);
                q += n - 2 - i;
            }
        }

        sum += acc0 * __ldg(x + j_a) + acc1 * __ldg(x + j_b);
    }

    // block reduction: warp shuffle -> smem -> warp 0 -> one atomic per block
    __shared__ float wsum[TPB / 32];
    float w = warp_sum(sum);
    if ((t & 31) == 0) wsum[t >> 5] = w;
    __syncthreads();
    if (t < 32) {
        float v = (t < TPB / 32) ? wsum[t] : 0.0f;
        v = warp_sum(v);
        if (t == 0) atomicAdd(out, v);
    }
}

extern "C" void kernel_launch(void* const* d_in, const int* in_sizes, int n_in,
                              void* d_out, int out_size) {
    const float* x = (const float*)d_in[0];
    const float* c = (const float*)d_in[1];
    float* out = (float*)d_out;
    const int n = in_sizes[0];   // 8192

    zero_out_kernel<<<1, 32>>>(out);
    ham_kernel<<<NBLOCKS, TPB>>>(x, c, out, n);
}